// round 2
// baseline (speedup 1.0000x reference)
#include <cuda_runtime.h>
#include <math.h>
#include <stdint.h>

#define NB     2
#define CIN    320
#define TT0    4
#define HW0    196
#define VPLANE 50176
#define VF     8
#define CDIM   768
#define TD     4
#define HH     53
#define HWD    2809
#define MPROJ  22472          // NB*TD*HWD
#define KPROJ  2304
#define NTOK   32
#define KF     2841
#define KFP    2848
#define BT3    6
#define MROWS  4608           // BT3*CDIM
#define EPSBN  1e-5

// ---------------- static scratch ----------------
__device__ float  g_scaleA[CIN], g_shiftA[CIN];
__device__ float  g_v[(size_t)NB*3*VF*VPLANE];
__device__ double g_redV[3*32*2];
__device__ float  g_scaleP[3], g_shiftP[3];
__device__ float  g_col[(size_t)MPROJ*KPROJ];
__device__ float  g_xp [(size_t)MPROJ*CDIM];
__device__ float  g_pos[(size_t)MPROJ*CDIM];
__device__ double g_sumT[CDIM], g_sumsqT[CDIM], g_sumC[CDIM], g_sumsqC[CDIM];
__device__ float  g_scaleT[CDIM], g_shiftT[CDIM];
__device__ float  g_scaleC[CDIM], g_shiftC[CDIM];
__device__ float  g_f0[(size_t)NB*HWD*CDIM];
__device__ float  g_d [(size_t)NB*HWD*CDIM];
__device__ float  g_sel[(size_t)NB*HWD*NTOK];
__device__ float  g_selmax[NB*NTOK];
__device__ float  g_tem [NB*NTOK*CDIM];
__device__ float  g_kmat[(size_t)MROWS*KFP];
__device__ float  g_fc1w[(size_t)KF*KFP];
__device__ float  g_fc2w[(size_t)HWD*KFP];
__device__ float  g_h   [(size_t)MROWS*KFP];
__device__ float  g_kpT [(size_t)BT3*HWD*CDIM];
__device__ float  g_score[(size_t)BT3*NTOK*HWD];
__device__ float  g_smax[BT3*NTOK];

// ---------------- zero accumulators ----------------
__global__ void k_zero() {
    int i = threadIdx.x;
    if (i < CDIM) { g_sumT[i]=0.0; g_sumsqT[i]=0.0; g_sumC[i]=0.0; g_sumsqC[i]=0.0; }
}

// ---------------- BN over x (320 ch) ----------------
__global__ void k_bn_a(const float* __restrict__ x, const float* __restrict__ g,
                       const float* __restrict__ b) {
    int c = blockIdx.x;
    double s = 0.0, s2 = 0.0;
    for (int i = threadIdx.x; i < NB*TT0*HW0; i += blockDim.x) {
        int bb = i / (TT0*HW0), r = i % (TT0*HW0);
        float v = x[((size_t)(bb*CIN + c))*(TT0*HW0) + r];
        s += v; s2 += (double)v * v;
    }
    __shared__ double sh[256], sh2[256];
    sh[threadIdx.x] = s; sh2[threadIdx.x] = s2;
    __syncthreads();
    for (int o = 128; o > 0; o >>= 1) {
        if (threadIdx.x < o) { sh[threadIdx.x] += sh[threadIdx.x+o]; sh2[threadIdx.x] += sh2[threadIdx.x+o]; }
        __syncthreads();
    }
    if (threadIdx.x == 0) {
        double n = (double)(NB*TT0*HW0);
        double mean = sh[0]/n, var = sh2[0]/n - mean*mean;
        float sc = (float)((double)g[c] / sqrt(var + EPSBN));
        g_scaleA[c] = sc;
        g_shiftA[c] = b[c] - (float)mean * sc;
    }
}

// ---------------- tconv + relu6 + residual -> g_v ----------------
// block handles 4 spatial positions, 256 threads
__global__ __launch_bounds__(256) void k_tconv(
    const float* __restrict__ x, const float* __restrict__ tw,
    const float* __restrict__ tb, const float* __restrict__ ori) {
    __shared__ float xs[4][CIN];
    int tid = threadIdx.x;
    for (int idx = tid; idx < 4*CIN; idx += 256) {
        int p = idx / CIN, i = idx % CIN;
        int lin = blockIdx.x * 4 + p;
        int w = lin % 14, h = (lin/14) % 14, t = (lin/196) % TT0, bb = lin/(196*TT0);
        xs[p][i] = x[((size_t)(bb*CIN+i)*TT0 + t)*HW0 + h*14 + w] * g_scaleA[i] + g_shiftA[i];
    }
    __syncthreads();
    for (int jj = tid; jj < 1536; jj += 256) {
        float a0=0.f, a1=0.f, a2=0.f, a3=0.f;
        const float* wp = tw + jj;
        #pragma unroll 4
        for (int i = 0; i < CIN; i++) {
            float wv = *wp; wp += 1536;
            a0 = fmaf(xs[0][i], wv, a0);
            a1 = fmaf(xs[1][i], wv, a1);
            a2 = fmaf(xs[2][i], wv, a2);
            a3 = fmaf(xs[3][i], wv, a3);
        }
        int o = jj >> 9, rem = jj & 511;
        int k = rem >> 8, p = (rem >> 4) & 15, q = rem & 15;
        float bias = tb[o];
        float accs[4] = {a0,a1,a2,a3};
        #pragma unroll
        for (int pp = 0; pp < 4; pp++) {
            int lin = blockIdx.x * 4 + pp;
            int w = lin % 14, h = (lin/14) % 14, t = (lin/196) % TT0, bb = lin/(196*TT0);
            float val = fminf(fmaxf(accs[pp] + bias, 0.f), 6.f);
            size_t oidx = ((size_t)(bb*3+o)*VF + (2*t+k))*VPLANE + (16*h+p)*224 + (16*w+q);
            g_v[oidx] = val + ori[oidx];
        }
    }
}

// ---------------- BN stats of v (3 ch) ----------------
__global__ void k_bnv_part() {
    int ch = blockIdx.x, part = blockIdx.y;
    const int per = (NB*VF*VPLANE) / 32;
    double s = 0.0, s2 = 0.0;
    int base = part * per;
    for (int i = threadIdx.x; i < per; i += blockDim.x) {
        int gi = base + i;
        int b = gi / (VF*VPLANE), r = gi % (VF*VPLANE);
        float v = g_v[((size_t)(b*3+ch))*VF*VPLANE + r];
        s += v; s2 += (double)v * v;
    }
    __shared__ double sh[256], sh2[256];
    sh[threadIdx.x] = s; sh2[threadIdx.x] = s2;
    __syncthreads();
    for (int o = 128; o > 0; o >>= 1) {
        if (threadIdx.x < o) { sh[threadIdx.x] += sh[threadIdx.x+o]; sh2[threadIdx.x] += sh2[threadIdx.x+o]; }
        __syncthreads();
    }
    if (threadIdx.x == 0) { g_redV[(ch*32+part)*2] = sh[0]; g_redV[(ch*32+part)*2+1] = sh2[0]; }
}
__global__ void k_bnv_final(const float* __restrict__ g, const float* __restrict__ b) {
    int ch = blockIdx.x;
    double s  = g_redV[(ch*32 + threadIdx.x)*2];
    double s2 = g_redV[(ch*32 + threadIdx.x)*2 + 1];
    for (int o = 16; o > 0; o >>= 1) {
        s  += __shfl_down_sync(0xffffffffu, s,  o);
        s2 += __shfl_down_sync(0xffffffffu, s2, o);
    }
    if (threadIdx.x == 0) {
        double n = (double)(NB*VF*VPLANE);
        double mean = s/n, var = s2/n - mean*mean;
        float sc = (float)((double)g[ch] / sqrt(var + EPSBN));
        g_scaleP[ch] = sc;
        g_shiftP[ch] = b[ch] - (float)mean * sc;
    }
}

// ---------------- im2col (BN folded, zero t-pad) ----------------
__global__ void k_im2col() {
    size_t idx = (size_t)blockIdx.x * 256 + threadIdx.x;
    if (idx >= (size_t)MPROJ * 576) return;
    int m  = (int)(idx / 576);
    int k4 = (int)(idx % 576) * 4;
    int c  = k4 / 768;
    int kt = (k4 % 768) / 256;
    int p  = (k4 % 256) / 16;
    int q  = k4 % 16;
    int w = m % HH, h = (m/HH) % HH, t = (m/HWD) % TD, b = m / (TD*HWD);
    int it = 2*t + kt - 1;
    float4 o;
    if (it < 0 || it > 7) {
        o = make_float4(0.f, 0.f, 0.f, 0.f);
    } else {
        const float* src = g_v + ((size_t)(b*3+c)*VF + it)*VPLANE + (4*h+p)*224 + (4*w+q);
        float4 v = *(const float4*)src;
        float sc = g_scaleP[c], sh = g_shiftP[c];
        o = make_float4(v.x*sc+sh, v.y*sc+sh, v.z*sc+sh, v.w*sc+sh);
    }
    *(float4*)(g_col + (size_t)m*KPROJ + k4) = o;
}

// ---------------- generic SGEMM: C[m,n] = sum_k A[m,k]*B[n,k] ----------------
// lda = ldb = K (all uses). mode 0: C[m*ldc+n]; mode 2: fc2 transposed store.
// act 1: exact gelu. z batching: A += (z/zdivA)*sAz, B += z*sBz, C += z*sCz.
__global__ __launch_bounds__(256) void k_sgemm(
    const float* __restrict__ A, const float* __restrict__ Bm,
    const float* __restrict__ bias, float* __restrict__ Cm,
    int M, int N, int K, int ldc, int act, int mode,
    long long sAz, int zdivA, long long sBz, long long sCz)
{
    int z = blockIdx.z;
    A  += (size_t)(z / zdivA) * sAz;
    Bm += (size_t)z * sBz;
    Cm += (size_t)z * sCz;
    __shared__ float As[8][128];
    __shared__ float Bs[8][128];
    const int tid  = threadIdx.x;
    const int lrow = tid >> 1, lcol = (tid & 1) << 2;
    const int m0 = blockIdx.y * 128, n0 = blockIdx.x * 128;
    const int ty = (tid >> 4) << 3, tx = (tid & 15) << 3;
    const bool am = (m0 + lrow) < M;
    const bool bn = (n0 + lrow) < N;
    const float* Ap = A  + (size_t)(m0+lrow)*K + lcol;
    const float* Bp = Bm + (size_t)(n0+lrow)*K + lcol;
    float acc[8][8];
    #pragma unroll
    for (int i = 0; i < 8; i++)
        #pragma unroll
        for (int j = 0; j < 8; j++) acc[i][j] = 0.f;

    for (int k0 = 0; k0 < K; k0 += 8) {
        float4 a4 = am ? *(const float4*)Ap : make_float4(0.f,0.f,0.f,0.f);
        float4 b4 = bn ? *(const float4*)Bp : make_float4(0.f,0.f,0.f,0.f);
        Ap += 8; Bp += 8;
        __syncthreads();
        As[lcol+0][lrow]=a4.x; As[lcol+1][lrow]=a4.y; As[lcol+2][lrow]=a4.z; As[lcol+3][lrow]=a4.w;
        Bs[lcol+0][lrow]=b4.x; Bs[lcol+1][lrow]=b4.y; Bs[lcol+2][lrow]=b4.z; Bs[lcol+3][lrow]=b4.w;
        __syncthreads();
        #pragma unroll
        for (int kk = 0; kk < 8; kk++) {
            float ar[8], br[8];
            #pragma unroll
            for (int i = 0; i < 8; i++) ar[i] = As[kk][ty+i];
            #pragma unroll
            for (int j = 0; j < 8; j++) br[j] = Bs[kk][tx+j];
            #pragma unroll
            for (int i = 0; i < 8; i++)
                #pragma unroll
                for (int j = 0; j < 8; j++)
                    acc[i][j] = fmaf(ar[i], br[j], acc[i][j]);
        }
    }
    // epilogue
    #pragma unroll
    for (int i = 0; i < 8; i++) {
        int m = m0 + ty + i;
        if (m >= M) continue;
        if (mode == 0) {
            #pragma unroll
            for (int j = 0; j < 8; j++) {
                int n = n0 + tx + j;
                if (n >= N) continue;
                float v = acc[i][j];
                if (bias) v += bias[n];
                if (act == 1) v = 0.5f * v * (1.f + erff(v * 0.70710678118654752f));
                Cm[(size_t)m*ldc + n] = v;
            }
        } else { // mode 2: kpT[z2][n][c] with z2=m/768, c=m%768
            int z2 = m / CDIM, c = m % CDIM;
            float* base = Cm + (size_t)z2*HWD*CDIM + c;
            #pragma unroll
            for (int j = 0; j < 8; j++) {
                int n = n0 + tx + j;
                if (n >= N) continue;
                float v = acc[i][j];
                if (bias) v += bias[n];
                base[(size_t)n*CDIM] = v;
            }
        }
    }
}

// ---------------- pos conv: depthwise 3x3x3 pad 1 on raw xp ----------------
__global__ __launch_bounds__(768) void k_pos(const float* __restrict__ pw,
                                             const float* __restrict__ pb) {
    int h = blockIdx.x, t = blockIdx.y, b = blockIdx.z;
    int c = threadIdx.x;
    float w27[27];
    #pragma unroll
    for (int i = 0; i < 27; i++) w27[i] = pw[c*27 + i];
    float bias = pb[c];
    float prv[9], cur[9], nxt[9];
    #pragma unroll
    for (int j = 0; j < 9; j++) { prv[j] = 0.f; cur[j] = 0.f; }
    // load column w=0
    #pragma unroll
    for (int j = 0; j < 9; j++) {
        int dt = j/3 - 1, dh = j%3 - 1;
        int tt = t + dt, hh = h + dh;
        cur[j] = (tt >= 0 && tt < TD && hh >= 0 && hh < HH)
                 ? g_xp[(((size_t)(b*TD+tt)*HWD) + hh*HH + 0)*CDIM + c] : 0.f;
    }
    for (int w = 0; w < HH; w++) {
        #pragma unroll
        for (int j = 0; j < 9; j++) {
            int dt = j/3 - 1, dh = j%3 - 1;
            int tt = t + dt, hh = h + dh;
            nxt[j] = (w+1 < HH && tt >= 0 && tt < TD && hh >= 0 && hh < HH)
                     ? g_xp[(((size_t)(b*TD+tt)*HWD) + hh*HH + (w+1))*CDIM + c] : 0.f;
        }
        float acc = bias;
        #pragma unroll
        for (int j = 0; j < 9; j++) {
            acc = fmaf(prv[j], w27[j*3+0], acc);
            acc = fmaf(cur[j], w27[j*3+1], acc);
            acc = fmaf(nxt[j], w27[j*3+2], acc);
        }
        g_pos[(((size_t)(b*TD+t)*HWD) + h*HH + w)*CDIM + c] = acc;
        #pragma unroll
        for (int j = 0; j < 9; j++) { prv[j] = cur[j]; cur[j] = nxt[j]; }
    }
}

// ---------------- BN stats (atomic two-phase) ----------------
__global__ void k_bnstat_t() {
    int tid = threadIdx.x;
    double s[3] = {0,0,0}, s2[3] = {0,0,0};
    int r0 = blockIdx.x * 256;
    for (int i = 0; i < 256; i++) {
        int r = r0 + i;
        if (r >= NB*HWD) break;
        int b = r / HWD, hw = r % HWD;
        size_t base = ((size_t)(b*TD)*HWD + hw)*CDIM;
        #pragma unroll
        for (int k = 0; k < 3; k++) {
            float v = g_xp[base + tid + 256*k];
            s[k] += v; s2[k] += (double)v * v;
        }
    }
    #pragma unroll
    for (int k = 0; k < 3; k++) {
        atomicAdd(&g_sumT[tid + 256*k],   s[k]);
        atomicAdd(&g_sumsqT[tid + 256*k], s2[k]);
    }
}
__global__ void k_bnstat_c() {
    int tid = threadIdx.x;
    double s[3] = {0,0,0}, s2[3] = {0,0,0};
    int r0 = blockIdx.x * 256;
    for (int i = 0; i < 256; i++) {
        int r = r0 + i;
        if (r >= MPROJ) break;
        size_t base = (size_t)r * CDIM;
        #pragma unroll
        for (int k = 0; k < 3; k++) {
            float v = g_xp[base + tid + 256*k];
            s[k] += v; s2[k] += (double)v * v;
        }
    }
    #pragma unroll
    for (int k = 0; k < 3; k++) {
        atomicAdd(&g_sumC[tid + 256*k],   s[k]);
        atomicAdd(&g_sumsqC[tid + 256*k], s2[k]);
    }
}
__global__ void k_bnfin(const float* gt, const float* bt,
                        const float* gc, const float* bc) {
    int c = threadIdx.x;
    {
        double n = (double)(NB*HWD);
        double mean = g_sumT[c]/n, var = g_sumsqT[c]/n - mean*mean;
        float sc = (float)((double)gt[c] / sqrt(var + EPSBN));
        g_scaleT[c] = sc; g_shiftT[c] = bt[c] - (float)mean * sc;
    }
    {
        double n = (double)MPROJ;
        double mean = g_sumC[c]/n, var = g_sumsqC[c]/n - mean*mean;
        float sc = (float)((double)gc[c] / sqrt(var + EPSBN));
        g_scaleC[c] = sc; g_shiftC[c] = bc[c] - (float)mean * sc;
    }
}

// ---------------- f0 = BN_t(xp frame 0) ----------------
__global__ void k_f0() {
    int r = blockIdx.x;           // b*HWD+hw
    int b = r / HWD, hw = r % HWD;
    size_t in  = ((size_t)(b*TD)*HWD + hw)*CDIM;
    size_t out = (size_t)r * CDIM;
    for (int c = threadIdx.x; c < CDIM; c += 256)
        g_f0[out + c] = g_xp[in + c] * g_scaleT[c] + g_shiftT[c];
}

// ---------------- token-selector depthwise 3x3 + hardswish ----------------
__global__ __launch_bounds__(768) void k_dw(const float* __restrict__ dw,
                                            const float* __restrict__ db) {
    int h = blockIdx.x, b = blockIdx.y;
    int c = threadIdx.x;
    float w9[9];
    #pragma unroll
    for (int i = 0; i < 9; i++) w9[i] = dw[c*9 + i];
    float bias = db[c];
    float prv[3], cur[3], nxt[3];
    #pragma unroll
    for (int j = 0; j < 3; j++) prv[j] = 0.f;
    #pragma unroll
    for (int j = 0; j < 3; j++) {
        int hh = h + j - 1;
        cur[j] = (hh >= 0 && hh < HH) ? g_f0[((size_t)b*HWD + hh*HH + 0)*CDIM + c] : 0.f;
    }
    for (int w = 0; w < HH; w++) {
        #pragma unroll
        for (int j = 0; j < 3; j++) {
            int hh = h + j - 1;
            nxt[j] = (w+1 < HH && hh >= 0 && hh < HH)
                     ? g_f0[((size_t)b*HWD + hh*HH + (w+1))*CDIM + c] : 0.f;
        }
        float acc = bias;
        #pragma unroll
        for (int j = 0; j < 3; j++) {
            acc = fmaf(prv[j], w9[j*3+0], acc);
            acc = fmaf(cur[j], w9[j*3+1], acc);
            acc = fmaf(nxt[j], w9[j*3+2], acc);
        }
        float hs = acc * fminf(fmaxf(acc + 3.f, 0.f), 6.f) * (1.f/6.f);
        g_d[((size_t)b*HWD + h*HH + w)*CDIM + c] = hs;
        #pragma unroll
        for (int j = 0; j < 3; j++) { prv[j] = cur[j]; cur[j] = nxt[j]; }
    }
}

// ---------------- sel = pw(d) ----------------
__global__ void k_sel(const float* __restrict__ pww, const float* __restrict__ pwb) {
    int hw = blockIdx.x, b = blockIdx.y;
    __shared__ float ds[CDIM];
    for (int c = threadIdx.x; c < CDIM; c += 256)
        ds[c] = g_d[((size_t)b*HWD + hw)*CDIM + c];
    __syncthreads();
    int n = threadIdx.x >> 3, sub = threadIdx.x & 7;
    float acc = 0.f;
    for (int c = sub; c < CDIM; c += 8)
        acc = fmaf(ds[c], pww[n*CDIM + c], acc);
    acc += __shfl_xor_sync(0xffffffffu, acc, 1);
    acc += __shfl_xor_sync(0xffffffffu, acc, 2);
    acc += __shfl_xor_sync(0xffffffffu, acc, 4);
    if (sub == 0) g_sel[((size_t)b*HWD + hw)*NTOK + n] = acc + pwb[n];
}

__global__ void k_selmax() {
    int n = blockIdx.x, b = blockIdx.y;
    float m = -3.4e38f;
    for (int hw = threadIdx.x; hw < HWD; hw += 256)
        m = fmaxf(m, g_sel[((size_t)b*HWD + hw)*NTOK + n]);
    __shared__ float sh[256];
    sh[threadIdx.x] = m;
    __syncthreads();
    for (int o = 128; o > 0; o >>= 1) {
        if (threadIdx.x < o) sh[threadIdx.x] = fmaxf(sh[threadIdx.x], sh[threadIdx.x+o]);
        __syncthreads();
    }
    if (threadIdx.x == 0) g_selmax[b*NTOK + n] = sh[0];
}

// ---------------- tem gather (deterministic ascending) ----------------
__global__ void k_temgather(float* __restrict__ out, float* __restrict__ outp) {
    int n = blockIdx.x, b = blockIdx.y;
    __shared__ unsigned char flag[HWD];
    float mx = g_selmax[b*NTOK + n];
    for (int hw = threadIdx.x; hw < HWD; hw += 256)
        flag[hw] = (g_sel[((size_t)b*HWD + hw)*NTOK + n] == mx) ? 1 : 0;
    __syncthreads();
    int c0 = threadIdx.x, c1 = threadIdx.x + 256, c2 = threadIdx.x + 512;
    float a0=0,a1=0,a2=0, p0=0,p1=0,p2=0;
    for (int hw = 0; hw < HWD; hw++) {
        if (flag[hw]) {
            size_t fb = ((size_t)b*HWD + hw)*CDIM;
            size_t pb = ((size_t)(b*TD)*HWD + hw)*CDIM;
            a0 += g_f0[fb+c0]; a1 += g_f0[fb+c1]; a2 += g_f0[fb+c2];
            p0 += g_pos[pb+c0]; p1 += g_pos[pb+c1]; p2 += g_pos[pb+c2];
        }
    }
    size_t tb = ((size_t)b*NTOK + n)*CDIM;
    g_tem[tb+c0]=a0; g_tem[tb+c1]=a1; g_tem[tb+c2]=a2;
    size_t ob = ((size_t)(b*TD + 0)*NTOK + n)*CDIM;
    out[ob+c0]=a0; out[ob+c1]=a1; out[ob+c2]=a2;
    outp[ob+c0]=p0; outp[ob+c1]=p1; outp[ob+c2]=p2;
}

// ---------------- build kmat [z*768+c][j], ld=2848 ----------------
__global__ void k_kmat() {
    int j = blockIdx.x * 128 + threadIdx.x;
    if (j >= KFP) return;
    int c = blockIdx.y, z = blockIdx.z;
    int b = z / 3, t = z % 3;
    float v;
    if (j < NTOK)      v = g_tem[((size_t)b*NTOK + j)*CDIM + c];
    else if (j < KF)   v = g_xp[((size_t)(b*TD + t + 1)*HWD + (j - NTOK))*CDIM + c]
                           * g_scaleC[c] + g_shiftC[c];
    else               v = 0.f;
    g_kmat[((size_t)z*CDIM + c)*KFP + j] = v;
}

// ---------------- pad weight copies ----------------
__global__ void k_padw(const float* __restrict__ src, float* __restrict__ dst,
                       int rows, int kin) {
    size_t idx = (size_t)blockIdx.x * 256 + threadIdx.x;
    if (idx >= (size_t)rows * KFP) return;
    int r = (int)(idx / KFP), k = (int)(idx % KFP);
    dst[idx] = (k < kin) ? src[(size_t)r*kin + k] : 0.f;
}

// ---------------- score max ----------------
__global__ void k_scoremax() {
    int n = blockIdx.x, z = blockIdx.y;
    float m = -3.4e38f;
    for (int hw = threadIdx.x; hw < HWD; hw += 256)
        m = fmaxf(m, g_score[((size_t)z*NTOK + n)*HWD + hw]);
    __shared__ float sh[256];
    sh[threadIdx.x] = m;
    __syncthreads();
    for (int o = 128; o > 0; o >>= 1) {
        if (threadIdx.x < o) sh[threadIdx.x] = fmaxf(sh[threadIdx.x], sh[threadIdx.x+o]);
        __syncthreads();
    }
    if (threadIdx.x == 0) g_smax[z*NTOK + n] = sh[0];
}

// ---------------- route gather -> out frames 1..3 ----------------
__global__ void k_route(float* __restrict__ out, float* __restrict__ outp) {
    int n = blockIdx.x, z = blockIdx.y;
    int b = z / 3, t = z % 3;
    __shared__ unsigned char flag[HWD];
    float mx = g_smax[z*NTOK + n];
    for (int hw = threadIdx.x; hw < HWD; hw += 256)
        flag[hw] = (g_score[((size_t)z*NTOK + n)*HWD + hw] == mx) ? 1 : 0;
    __syncthreads();
    int c0 = threadIdx.x, c1 = threadIdx.x + 256, c2 = threadIdx.x + 512;
    float s0=0,s1=0,s2=0, p0=0,p1=0,p2=0;
    int cnt = 0;
    for (int hw = 0; hw < HWD; hw++) {
        if (flag[hw]) {
            size_t xb = ((size_t)(b*TD + t + 1)*HWD + hw)*CDIM;
            s0 += g_xp[xb+c0]; s1 += g_xp[xb+c1]; s2 += g_xp[xb+c2];
            p0 += g_pos[xb+c0]; p1 += g_pos[xb+c1]; p2 += g_pos[xb+c2];
            cnt++;
        }
    }
    float fc = (float)cnt;
    size_t ob = ((size_t)(b*TD + t + 1)*NTOK + n)*CDIM;
    out[ob+c0] = g_scaleC[c0]*s0 + fc*g_shiftC[c0];
    out[ob+c1] = g_scaleC[c1]*s1 + fc*g_shiftC[c1];
    out[ob+c2] = g_scaleC[c2]*s2 + fc*g_shiftC[c2];
    outp[ob+c0] = p0; outp[ob+c1] = p1; outp[ob+c2] = p2;
}

// ---------------- launch ----------------
extern "C" void kernel_launch(void* const* d_in, const int* in_sizes, int n_in,
                              void* d_out, int out_size) {
    const float* x       = (const float*)d_in[0];
    const float* ori     = (const float*)d_in[1];
    const float* bn_a_g  = (const float*)d_in[2];
    const float* bn_a_b  = (const float*)d_in[3];
    const float* tconv_w = (const float*)d_in[4];
    const float* tconv_b = (const float*)d_in[5];
    const float* bn_p_g  = (const float*)d_in[6];
    const float* bn_p_b  = (const float*)d_in[7];
    const float* proj_w  = (const float*)d_in[8];
    const float* proj_b  = (const float*)d_in[9];
    const float* pos_w   = (const float*)d_in[10];
    const float* pos_b   = (const float*)d_in[11];
    const float* bn_t_g  = (const float*)d_in[12];
    const float* bn_t_b  = (const float*)d_in[13];
    const float* dw_w    = (const float*)d_in[14];
    const float* dw_b    = (const float*)d_in[15];
    const float* pw_w    = (const float*)d_in[16];
    const float* pw_b    = (const float*)d_in[17];
    const float* bn_c_g  = (const float*)d_in[18];
    const float* bn_c_b  = (const float*)d_in[19];
    const float* fc1_w   = (const float*)d_in[20];
    const float* fc1_b   = (const float*)d_in[21];
    const float* fc2_w   = (const float*)d_in[22];
    const float* fc2_b   = (const float*)d_in[23];

    float* out  = (float*)d_out;
    float* outp = out + out_size / 2;

    float *p_col, *p_xp, *p_h, *p_kpT, *p_tem, *p_score, *p_kmat, *p_fc1w, *p_fc2w;
    cudaGetSymbolAddress((void**)&p_col,   g_col);
    cudaGetSymbolAddress((void**)&p_xp,    g_xp);
    cudaGetSymbolAddress((void**)&p_h,     g_h);
    cudaGetSymbolAddress((void**)&p_kpT,   g_kpT);
    cudaGetSymbolAddress((void**)&p_tem,   g_tem);
    cudaGetSymbolAddress((void**)&p_score, g_score);
    cudaGetSymbolAddress((void**)&p_kmat,  g_kmat);
    cudaGetSymbolAddress((void**)&p_fc1w,  g_fc1w);
    cudaGetSymbolAddress((void**)&p_fc2w,  g_fc2w);

    k_zero<<<1, 768>>>();
    k_bn_a<<<CIN, 256>>>(x, bn_a_g, bn_a_b);
    k_tconv<<<392, 256>>>(x, tconv_w, tconv_b, ori);
    k_bnv_part<<<dim3(3, 32), 256>>>();
    k_bnv_final<<<3, 32>>>(bn_p_g, bn_p_b);
    k_im2col<<<(int)(((size_t)MPROJ*576 + 255)/256), 256>>>();
    // proj: M=22472, N=768, K=2304
    k_sgemm<<<dim3(6, 176, 1), 256>>>(p_col, proj_w, proj_b, p_xp,
                                      MPROJ, CDIM, KPROJ, CDIM, 0, 0, 0, 1, 0, 0);
    k_pos<<<dim3(HH, TD, NB), 768>>>(pos_w, pos_b);
    k_bnstat_t<<<22, 256>>>();
    k_bnstat_c<<<88, 256>>>();
    k_bnfin<<<1, 768>>>(bn_t_g, bn_t_b, bn_c_g, bn_c_b);
    k_f0<<<NB*HWD, 256>>>();
    k_dw<<<dim3(HH, NB), 768>>>(dw_w, dw_b);
    k_sel<<<dim3(HWD, NB), 256>>>(pw_w, pw_b);
    k_selmax<<<dim3(NTOK, NB), 256>>>();
    k_temgather<<<dim3(NTOK, NB), 256>>>(out, outp);
    k_kmat<<<dim3((KFP+127)/128, CDIM, BT3), 128>>>();
    k_padw<<<(int)(((size_t)KF*KFP + 255)/256), 256>>>(fc1_w, p_fc1w, KF, KF);
    k_padw<<<(int)(((size_t)HWD*KFP + 255)/256), 256>>>(fc2_w, p_fc2w, HWD, KF);
    // fc1: M=4608, N=2841, K=2848, gelu, ldc=2848
    k_sgemm<<<dim3(23, 36, 1), 256>>>(p_kmat, p_fc1w, fc1_b, p_h,
                                      MROWS, KF, KFP, KFP, 1, 0, 0, 1, 0, 0);
    // fc2: M=4608, N=2809, K=2848, transposed store -> kpT
    k_sgemm<<<dim3(22, 36, 1), 256>>>(p_h, p_fc2w, fc2_b, p_kpT,
                                      MROWS, HWD, KFP, 0, 0, 2, 0, 1, 0, 0);
    // score: z=6, M=32, N=2809, K=768
    k_sgemm<<<dim3(22, 1, BT3), 256>>>(p_tem, p_kpT, nullptr, p_score,
                                      NTOK, HWD, CDIM, HWD, 0, 0,
                                      (long long)NTOK*CDIM, 3,
                                      (long long)HWD*CDIM,
                                      (long long)NTOK*HWD);
    k_scoremax<<<dim3(NTOK, BT3), 256>>>();
    k_route<<<dim3(NTOK, BT3), 256>>>(out, outp);
}